// round 2
// baseline (speedup 1.0000x reference)
#include <cuda_runtime.h>

#define BB 4
#define CC 128
#define HIN 512
#define WIN 512
#define HS 128
#define KPAD 4
#define HP 136
#define NG 4
#define CG 32
#define NOFF 81
#define EPSV 1e-8f

// ---------------- scratch (static device allocations are allowed) ----------
__device__ float g_xs[BB*CC*HS*HS];   // downsampled x            (33.5 MB)
__device__ float g_yp[BB*CC*HP*HP];   // downsampled+reflect-pad y (37.9 MB)
__device__ float g_yc[BB*CC*HP*HP];   // conv output               (37.9 MB)
__device__ float g_nx[BB*NG*HS*HS];   // max(||x||_g, eps)
__device__ float g_ny[BB*NG*HP*HP];   // ||yc||_g (raw)

// ---------------- bilinear downsample helpers ------------------------------
__device__ __forceinline__ float bilin512(const float* __restrict__ p, int ti, int tj) {
    // sample the 512x512 plane p at align-corners position of (ti,tj) in 128-grid
    const double scale = 511.0 / 127.0;
    double py = ti * scale, px = tj * scale;
    int y0 = (int)py, x0 = (int)px;
    float fy = (float)(py - (double)y0);
    float fx = (float)(px - (double)x0);
    int y1 = min(y0 + 1, 511), x1 = min(x0 + 1, 511);
    const float* r0 = p + y0 * WIN;
    const float* r1 = p + y1 * WIN;
    float a = r0[x0], b = r0[x1], c = r1[x0], d = r1[x1];
    float top = a + (b - a) * fx;
    float bot = c + (d - c) * fx;
    return top + (bot - top) * fy;
}

__global__ void downsample_x_kernel(const float* __restrict__ x) {
    int idx = blockIdx.x * 256 + threadIdx.x;       // BB*CC*HS*HS threads
    int j  = idx & 127;
    int i  = (idx >> 7) & 127;
    int bc = idx >> 14;
    const float* p = x + (size_t)bc * HIN * WIN;
    g_xs[idx] = bilin512(p, i, j);
}

__global__ void downsample_y_pad_kernel(const float* __restrict__ y) {
    int idx = blockIdx.x * 256 + threadIdx.x;       // BB*CC*HP*HP threads
    if (idx >= BB*CC*HP*HP) return;
    int n  = idx % HP;
    int m  = (idx / HP) % HP;
    int bc = idx / (HP * HP);
    int t = m - KPAD; if (t < 0) t = -t; if (t > 127) t = 254 - t;   // reflect
    int s = n - KPAD; if (s < 0) s = -s; if (s > 127) s = 254 - s;
    const float* p = y + (size_t)bc * HIN * WIN;
    g_yp[idx] = bilin512(p, t, s);
}

// ---------------- 3x3 conv, 128->128, zero pad 1, on 136x136 ---------------
// tile: 64 oc x 16h x 16w, 256 threads: 8 oc-threads x 32 px-threads
// thread: 8 oc x 8 px (64 accums). LDS/FMA = 1 B/FMA -> fma-issue bound.
#define ICB 8
__global__ void conv3x3_kernel(const float* __restrict__ Wt,
                               const float* __restrict__ bias) {
    __shared__ float ins[ICB][18][19];   // padded pitch 19 -> conflict-free
    __shared__ float ws[ICB][9][65];     // pitch 65 -> conflict-free STS

    int bz  = blockIdx.z;            // b*2 + ocblk
    int b   = bz >> 1;
    int oc0 = (bz & 1) * 64;
    int m0  = blockIdx.y * 16;
    int n0  = blockIdx.x * 16;
    int tid = threadIdx.x;
    int pxt = tid & 31;
    int oct = tid >> 5;              // warp id == oc-thread -> w LDS broadcast
    int ti  = pxt >> 1;
    int tjb = (pxt & 1) * 8;

    float acc[8][8];
    #pragma unroll
    for (int r = 0; r < 8; r++)
        #pragma unroll
        for (int k = 0; k < 8; k++) acc[r][k] = 0.f;

    const float* yp_b = g_yp + (size_t)b * CC * HP * HP;

    for (int ic0 = 0; ic0 < CC; ic0 += ICB) {
        __syncthreads();
        // input tile ICB x 18 x 18 (zero-pad boundary of +-1)
        for (int e = tid; e < ICB * 18 * 18; e += 256) {
            int col = e % 18;
            int row = (e / 18) % 18;
            int ic  = e / (18 * 18);
            int mm = m0 - 1 + row, nn = n0 - 1 + col;
            float v = 0.f;
            if (mm >= 0 && mm < HP && nn >= 0 && nn < HP)
                v = yp_b[(size_t)(ic0 + ic) * HP * HP + mm * HP + nn];
            ins[ic][row][col] = v;
        }
        // weights: 64 oc x ICB x 9, coalesced src (144-float runs per oc)
        for (int e = tid; e < 64 * ICB * 9; e += 256) {
            int ocl = e / (ICB * 9);
            int r   = e % (ICB * 9);
            float v = Wt[(size_t)(oc0 + ocl) * (CC * 9) + ic0 * 9 + r];
            ws[r / 9][r % 9][ocl] = v;
        }
        __syncthreads();

        #pragma unroll 1
        for (int ic = 0; ic < ICB; ic++) {
            #pragma unroll
            for (int di = 0; di < 3; di++) {
                #pragma unroll
                for (int dj = 0; dj < 3; dj++) {
                    float wv[8], iv[8];
                    #pragma unroll
                    for (int r = 0; r < 8; r++) wv[r] = ws[ic][di*3+dj][oct*8 + r];
                    #pragma unroll
                    for (int k = 0; k < 8; k++) iv[k] = ins[ic][ti + di][tjb + dj + k];
                    #pragma unroll
                    for (int r = 0; r < 8; r++)
                        #pragma unroll
                        for (int k = 0; k < 8; k++)
                            acc[r][k] = fmaf(wv[r], iv[k], acc[r][k]);
                }
            }
        }
    }

    int m  = m0 + ti;
    int nb = n0 + tjb;
    if (m < HP) {
        #pragma unroll
        for (int r = 0; r < 8; r++) {
            int oc = oc0 + oct * 8 + r;
            float bi = bias[oc];
            float* outp = g_yc + ((size_t)b * CC + oc) * HP * HP + m * HP + nb;
            #pragma unroll
            for (int k = 0; k < 8; k++)
                if (nb + k < HP) outp[k] = acc[r][k] + bi;
        }
    }
}

// ---------------- group norms ----------------------------------------------
__global__ void norm_x_kernel() {
    int idx = blockIdx.x * 256 + threadIdx.x;     // BB*NG*HS*HS
    if (idx >= BB * NG * HS * HS) return;
    int px = idx % (HS * HS);
    int bg = idx / (HS * HS);
    int b = bg >> 2, g = bg & 3;
    const float* p = g_xs + ((size_t)b * CC + g * CG) * HS * HS + px;
    float s = 0.f;
    #pragma unroll
    for (int c = 0; c < CG; c++) { float v = p[(size_t)c * HS * HS]; s = fmaf(v, v, s); }
    g_nx[idx] = fmaxf(sqrtf(s), EPSV);
}

__global__ void norm_y_kernel() {
    int idx = blockIdx.x * 256 + threadIdx.x;     // BB*NG*HP*HP
    if (idx >= BB * NG * HP * HP) return;
    int px = idx % (HP * HP);
    int bg = idx / (HP * HP);
    int b = bg >> 2, g = bg & 3;
    const float* p = g_yc + ((size_t)b * CC + g * CG) * HP * HP + px;
    float s = 0.f;
    #pragma unroll
    for (int c = 0; c < CG; c++) { float v = p[(size_t)c * HP * HP]; s = fmaf(v, v, s); }
    g_ny[idx] = sqrtf(s);
}

// ---------------- 81-offset correlation -------------------------------------
// block: (b,g) x 8h x 32w tile; thread = 1 pixel; x channels in registers;
// y group slab 32ch x 16 x 40 in dynamic SMEM. Warp = one row of 32 cols ->
// all LDS conflict-free (consecutive addresses).
#define CORR_SY (CG * 16 * 40)
#define CORR_SN (16 * 40)
#define CORR_SMEM ((CORR_SY + CORR_SN) * 4)

__global__ void corr_kernel(float* __restrict__ out) {
    extern __shared__ float sm[];
    float* sy = sm;                 // [c][row][col] flat, pitch 40
    float* sn = sm + CORR_SY;       // reciprocal of max(ny,eps), pitch 40

    int bg = blockIdx.z;            // b*4+g
    int b  = bg >> 2, g = bg & 3;
    int i0 = blockIdx.y * 8;
    int j0 = blockIdx.x * 32;
    int tid = threadIdx.x;          // 256
    int tj = tid & 31, ti = tid >> 5;

    const float* ycb = g_yc + ((size_t)b * CC + g * CG) * HP * HP;
    for (int e = tid; e < CG * 16 * 40; e += 256) {
        int col = e % 40;
        int row = (e / 40) % 16;
        int c   = e / (16 * 40);
        sy[e] = ycb[(size_t)c * HP * HP + (i0 + row) * HP + (j0 + col)];
    }
    const float* nyb = g_ny + (size_t)bg * HP * HP;
    for (int e = tid; e < 16 * 40; e += 256) {
        int col = e % 40, row = e / 40;
        sn[e] = 1.0f / fmaxf(nyb[(i0 + row) * HP + (j0 + col)], EPSV);
    }
    __syncthreads();

    float xr[CG];
    const float* xsb = g_xs + ((size_t)b * CC + g * CG) * HS * HS
                            + (i0 + ti) * HS + (j0 + tj);
    #pragma unroll
    for (int c = 0; c < CG; c++) xr[c] = xsb[(size_t)c * HS * HS];

    float inx = 1.0f / g_nx[(size_t)bg * HS * HS + (i0 + ti) * HS + (j0 + tj)];
    float* outp = out + (size_t)bg * NOFF * HS * HS + (i0 + ti) * HS + (j0 + tj);

    #pragma unroll 1
    for (int oi = 0; oi < 9; oi++) {
        #pragma unroll 1
        for (int oj = 0; oj < 9; oj++) {
            float acc = 0.f;
            int base = (ti + oi) * 40 + tj + oj;
            #pragma unroll
            for (int c = 0; c < CG; c++)
                acc = fmaf(xr[c], sy[c * (16 * 40) + base], acc);
            float r = sn[base];
            outp[(size_t)(oi * 9 + oj) * (HS * HS)] = acc * inx * r;
        }
    }
}

// ---------------- launcher ---------------------------------------------------
extern "C" void kernel_launch(void* const* d_in, const int* in_sizes, int n_in,
                              void* d_out, int out_size) {
    const float* x     = (const float*)d_in[0];
    const float* y     = (const float*)d_in[1];
    const float* Wt    = (const float*)d_in[2];
    const float* bconv = (const float*)d_in[3];
    float* out = (float*)d_out;

    cudaFuncSetAttribute(corr_kernel,
                         cudaFuncAttributeMaxDynamicSharedMemorySize, CORR_SMEM);

    downsample_x_kernel<<<(BB*CC*HS*HS) / 256, 256>>>(x);
    downsample_y_pad_kernel<<<(BB*CC*HP*HP + 255) / 256, 256>>>(y);
    conv3x3_kernel<<<dim3(9, 9, BB * 2), 256>>>(Wt, bconv);
    norm_x_kernel<<<(BB*NG*HS*HS + 255) / 256, 256>>>();
    norm_y_kernel<<<(BB*NG*HP*HP + 255) / 256, 256>>>();
    corr_kernel<<<dim3(4, 16, BB * NG), 256, CORR_SMEM>>>(out);
}